// round 16
// baseline (speedup 1.0000x reference)
#include <cuda_runtime.h>
#include <math.h>
#include <stdint.h>

#define B_ 64
#define T_ 256
#define I_ 512
#define S_ 256
#define D_ 1024
#define H_ 1024
#define R_ 1280

#define GBLK 128
#define TPB  512
#define JPB  8
#define SPB  2

typedef unsigned long long ull;

#define N_WHH  (24 * 1024)
#define N_WIH  (24 * 256)
#define N_WMVH (4 * 1024)
#define OFF_WIH   (N_WHH)
#define OFF_WMVH  (OFF_WIH + N_WIH)
#define OFF_STG   (OFF_WMVH + N_WMVH)
#define OFF_B     (OFF_STG + 16384)
#define SCAN_SMEM_FLOATS (OFF_B + 64)
#define SCAN_SMEM_BYTES  (SCAN_SMEM_FLOATS * 4)

__device__ __align__(256) float g_h[D_ * B_];
__device__ __align__(256) float g_z[S_ * B_];
__device__ __align__(256) float g_wx[2 * S_ * I_];
__device__ __align__(256) float g_bx[2 * S_];
__device__ __align__(256) float g_postx[(size_t)B_ * T_ * 2 * S_];
__device__ __align__(256) float g_rssm[(size_t)B_ * T_ * R_];
__device__ __align__(256) float g_a0[(size_t)B_ * T_ * H_];
__device__ __align__(256) float g_a1[(size_t)B_ * T_ * H_];
__device__ __align__(256) float g_dist[(size_t)B_ * T_ * I_];

__device__ unsigned g_arrive[GBLK * 32];
__device__ unsigned g_release;

__device__ __forceinline__ void ffma2(ull& d, ull a, ull b) {
    asm("fma.rn.f32x2 %0, %1, %2, %0;" : "+l"(d) : "l"(a), "l"(b));
}
__device__ __forceinline__ float sum2(ull v) {
    return __uint_as_float((unsigned)v) + __uint_as_float((unsigned)(v >> 32));
}
__device__ __forceinline__ uint32_t smem_u32h(const void* p) {
    uint32_t a;
    asm("{ .reg .u64 t; cvta.to.shared.u64 t, %1; cvt.u32.u64 %0, t; }" : "=r"(a) : "l"(p));
    return a;
}
__device__ __forceinline__ void cpa16(unsigned dst, const void* src) {
    asm volatile("cp.async.cg.shared.global [%0], [%1], 16;" :: "r"(dst), "l"(src));
}
#define CP_COMMIT() asm volatile("cp.async.commit_group;" ::: "memory")
#define CP_WAIT0()  asm volatile("cp.async.wait_group 0;" ::: "memory")
#define CP_WAIT1()  asm volatile("cp.async.wait_group 1;" ::: "memory")

__device__ __forceinline__ void grid_sync(unsigned token) {
    __syncthreads();
    if (blockIdx.x == 0) {
        if (threadIdx.x > 0 && threadIdx.x < GBLK) {
            unsigned v;
            do { asm volatile("ld.acquire.gpu.global.u32 %0, [%1];" : "=r"(v) : "l"(g_arrive + threadIdx.x * 32) : "memory"); } while (v < token);
        }
        __syncthreads();
        if (threadIdx.x == 0)
            asm volatile("st.release.gpu.global.u32 [%0], %1;" :: "l"(&g_release), "r"(token) : "memory");
    } else {
        if (threadIdx.x == 0) {
            asm volatile("st.release.gpu.global.u32 [%0], %1;" :: "l"(g_arrive + blockIdx.x * 32), "r"(token) : "memory");
            unsigned v;
            do { asm volatile("ld.acquire.gpu.global.u32 %0, [%1];" : "=r"(v) : "l"(&g_release) : "memory"); } while (v < token);
        }
        __syncthreads();
    }
}

__device__ __forceinline__ void cpa_team(unsigned dstu, const float4* src, int ttid) {
#pragma unroll
    for (int i = 0; i < 4; ++i)
        cpa16(dstu + (unsigned)((ttid + i * 128) * 16), src + ttid + i * 128);
}
__device__ __forceinline__ void teambar(int team) {
    asm volatile("bar.sync %0, 128;" :: "r"(team + 1) : "memory");
}

template<bool POST>
__device__ __forceinline__ void gchunk2(const float* __restrict__ sb,
        const float* __restrict__ ar, const float* __restrict__ az,
        const float* __restrict__ an,
        const float* __restrict__ br, const float* __restrict__ bz,
        const float* __restrict__ bn, const float* __restrict__ wp,
        ull& rA0, ull& rA1, ull& zA0, ull& zA1, ull& nA0, ull& nA1,
        ull& rB0, ull& rB1, ull& zB0, ull& zB1, ull& nB0, ull& nB1,
        ull& P0, ull& P1)
{
#pragma unroll
    for (int i = 0; i < 8; ++i) {
        ulonglong2 a0 = *(const ulonglong2*)(sb + (2 * i) * 128);
        ulonglong2 a1 = *(const ulonglong2*)(sb + (2 * i + 1) * 128);
        ulonglong2 q;
        q = *(const ulonglong2*)(ar + 4 * i);
        ffma2(rA0, q.x, a0.x); ffma2(rA0, q.y, a1.x);
        ffma2(rA1, q.x, a0.y); ffma2(rA1, q.y, a1.y);
        q = *(const ulonglong2*)(az + 4 * i);
        ffma2(zA0, q.x, a0.x); ffma2(zA0, q.y, a1.x);
        ffma2(zA1, q.x, a0.y); ffma2(zA1, q.y, a1.y);
        q = *(const ulonglong2*)(an + 4 * i);
        ffma2(nA0, q.x, a0.x); ffma2(nA0, q.y, a1.x);
        ffma2(nA1, q.x, a0.y); ffma2(nA1, q.y, a1.y);
        q = *(const ulonglong2*)(br + 4 * i);
        ffma2(rB0, q.x, a0.x); ffma2(rB0, q.y, a1.x);
        ffma2(rB1, q.x, a0.y); ffma2(rB1, q.y, a1.y);
        q = *(const ulonglong2*)(bz + 4 * i);
        ffma2(zB0, q.x, a0.x); ffma2(zB0, q.y, a1.x);
        ffma2(zB1, q.x, a0.y); ffma2(zB1, q.y, a1.y);
        q = *(const ulonglong2*)(bn + 4 * i);
        ffma2(nB0, q.x, a0.x); ffma2(nB0, q.y, a1.x);
        ffma2(nB1, q.x, a0.y); ffma2(nB1, q.y, a1.y);
        if (POST) {
            q = *(const ulonglong2*)(wp + 4 * i);
            ffma2(P0, q.x, a0.x); ffma2(P0, q.y, a1.x);
            ffma2(P1, q.x, a0.y); ffma2(P1, q.y, a1.y);
        }
    }
}

__device__ __forceinline__ float gru_cell(float vr, float vz, float gi, float gh, float hp) {
    float r = 1.f / (1.f + __expf(-vr));
    float z = 1.f / (1.f + __expf(-vz));
    float n = tanhf(gi + r * gh);
    return (1.f - z) * n + z * hp;
}

__global__ void init_state_kernel() {
    const int idx = blockIdx.x * blockDim.x + threadIdx.x;
    const int stride = gridDim.x * blockDim.x;
    for (int i = idx; i < D_ * B_; i += stride) g_h[i] = 0.f;
    for (int i = idx; i < S_ * B_; i += stride) g_z[i] = 0.f;
    for (int i = idx; i < GBLK * 32; i += stride) g_arrive[i] = 0u;
    if (idx == 0) g_release = 0u;
}

__global__ void build_wx_kernel(const float* __restrict__ Wm, const float* __restrict__ Wv,
                                const float* __restrict__ bm, const float* __restrict__ bv) {
    const int n = blockIdx.x;
    const int s = n >> 1, mv = n & 1;
    const float* src = (mv ? Wv : Wm) + (size_t)s * (I_ + D_);
    float* dst = g_wx + (size_t)n * I_;
    for (int k = threadIdx.x; k < I_; k += blockDim.x) dst[k] = src[k];
    if (threadIdx.x == 0) g_bx[n] = mv ? bv[s] : bm[s];
}

// ---------------- scan (identical to R13) ----------------
__global__ void __launch_bounds__(TPB, 1) scan_kernel(
    const float* __restrict__ W_ih, const float* __restrict__ W_hh,
    const float* __restrict__ b_ih, const float* __restrict__ b_hh,
    const float* __restrict__ Wm,   const float* __restrict__ Wv,
    const float* __restrict__ noise)
{
    extern __shared__ float sm[];
    float* s_whh  = sm;
    float* s_wih  = sm + OFF_WIH;
    float* s_wmvh = sm + OFF_WMVH;
    float* s_stg  = sm + OFF_STG;
    float* s_bih  = sm + OFF_B;
    float* s_bhh  = sm + OFF_B + 24;
    const unsigned stg_u = smem_u32h(s_stg);
    const int tid  = threadIdx.x;
    const int lane = tid & 31;
    const int wid  = tid >> 5;
    const int team = wid >> 2;
    const int ttid = tid & 127;
    const int wj   = wid & 3;
    const int bid  = blockIdx.x;
    const int j0g  = bid * JPB;
    const int s0g  = bid * SPB;
    const int jl0  = 2 * wj, jl1 = 2 * wj + 1;

    for (int v = tid; v < 24 * 256; v += TPB) {
        int row = v >> 8, c = v & 255;
        int jl = row / 3, g = row % 3;
        ((float4*)s_whh)[v] = ((const float4*)(W_hh + (size_t)(g * D_ + j0g + jl) * D_))[c];
    }
    for (int v = tid; v < 24 * 64; v += TPB) {
        int row = v >> 6, c = v & 63;
        int jl = row / 3, g = row % 3;
        ((float4*)s_wih)[v] = ((const float4*)(W_ih + (size_t)(g * D_ + j0g + jl) * S_))[c];
    }
    for (int v = tid; v < 4 * 256; v += TPB) {
        int row = v >> 8, c = v & 255;
        int sl = row >> 1, mv = row & 1;
        const float* W = (mv ? Wv : Wm) + (size_t)(s0g + sl) * (I_ + D_) + I_;
        ((float4*)s_wmvh)[v] = ((const float4*)W)[c];
    }
    if (tid < 24) {
        int jl = tid / 3, g = tid % 3;
        s_bih[tid] = b_ih[g * D_ + j0g + jl];
        s_bhh[tid] = b_hh[g * D_ + j0g + jl];
    }
    __syncthreads();

    const float* ihAr = s_wih + (jl0 * 3 + 0) * S_;
    const float* ihAz = s_wih + (jl0 * 3 + 1) * S_;
    const float* ihAn = s_wih + (jl0 * 3 + 2) * S_;
    const float* ihBr = s_wih + (jl1 * 3 + 0) * S_;
    const float* ihBz = s_wih + (jl1 * 3 + 1) * S_;
    const float* ihBn = s_wih + (jl1 * 3 + 2) * S_;
    const float* hhAr = s_whh + (jl0 * 3 + 0) * D_;
    const float* hhAz = s_whh + (jl0 * 3 + 1) * D_;
    const float* hhAn = s_whh + (jl0 * 3 + 2) * D_;
    const float* hhBr = s_whh + (jl1 * 3 + 0) * D_;
    const float* hhBz = s_whh + (jl1 * 3 + 1) * D_;
    const float* hhBn = s_whh + (jl1 * 3 + 2) * D_;
    const float* wpR  = s_wmvh + wj * D_;

    const unsigned tb0 = stg_u + (unsigned)team * 16384u;
    const unsigned tb1 = tb0 + 8192u;
    const float* sb0 = s_stg + team * 4096 + 4 * lane;
    const float* sb1 = sb0 + 2048;
    const float4* zsrc = (const float4*)g_z + team * 512;
    const float4* hsrc = (const float4*)g_h + team * 512;

    ull rA0 = 0, rA1 = 0, zA0 = 0, zA1 = 0, nA0 = 0, nA1 = 0;
    ull rB0 = 0, rB1 = 0, zB0 = 0, zB1 = 0, nB0 = 0, nB1 = 0;
    float hp0 = 0.f, hp1 = 0.f, hp2 = 0.f, hp3 = 0.f;
    ull du0, du1;

    cpa_team(tb0, zsrc, ttid); CP_COMMIT();

    for (int t = 0; t < T_; ++t) {
        float2 px = make_float2(0.f, 0.f);
        float nz = 0.f;
        if (tid < 128) {
            int slq = tid >> 6, bq = tid & 63;
            px = __ldcg((const float2*)(g_postx + ((size_t)bq * T_ + t) * (2 * S_) + 2 * (s0g + slq)));
            nz = __ldcg(noise + ((size_t)t * B_ + bq) * S_ + s0g + slq);
        }

        ull gA0 = 0, gA1 = 0, gB0 = 0, gB1 = 0;
        {
            CP_WAIT0(); teambar(team);
            cpa_team(tb1, zsrc + 2048, ttid); CP_COMMIT();
            int off = team * 32;
            gchunk2<false>(sb0, ihAr + off, ihAz + off, ihAn + off,
                           ihBr + off, ihBz + off, ihBn + off, 0,
                           rA0, rA1, zA0, zA1, gA0, gA1,
                           rB0, rB1, zB0, zB1, gB0, gB1, du0, du1);
            CP_WAIT0(); teambar(team);
            off = 128 + team * 32;
            gchunk2<false>(sb1, ihAr + off, ihAz + off, ihAn + off,
                           ihBr + off, ihBz + off, ihBn + off, 0,
                           rA0, rA1, zA0, zA1, gA0, gA1,
                           rB0, rB1, zB0, zB1, gB0, gB1, du0, du1);
        }
        {
            __syncthreads();
            if (team != 0) {
                float* r = s_stg + ((team - 1) * 4 + wj) * 544 + lane * 17;
                r[0]  = sum2(rA0); r[1]  = sum2(rA1);
                r[2]  = sum2(zA0); r[3]  = sum2(zA1);
                r[4]  = sum2(gA0); r[5]  = sum2(gA1);
                r[6]  = sum2(nA0); r[7]  = sum2(nA1);
                r[8]  = sum2(rB0); r[9]  = sum2(rB1);
                r[10] = sum2(zB0); r[11] = sum2(zB1);
                r[12] = sum2(gB0); r[13] = sum2(gB1);
                r[14] = sum2(nB0); r[15] = sum2(nB1);
            }
            __syncthreads();
            if (team == 0) {
                float s[16];
                s[0]=sum2(rA0); s[1]=sum2(rA1); s[2]=sum2(zA0); s[3]=sum2(zA1);
                s[4]=sum2(gA0); s[5]=sum2(gA1); s[6]=sum2(nA0); s[7]=sum2(nA1);
                s[8]=sum2(rB0); s[9]=sum2(rB1); s[10]=sum2(zB0); s[11]=sum2(zB1);
                s[12]=sum2(gB0); s[13]=sum2(gB1); s[14]=sum2(nB0); s[15]=sum2(nB1);
#pragma unroll
                for (int tm = 0; tm < 3; ++tm) {
                    const float* r = s_stg + (tm * 4 + wj) * 544 + lane * 17;
#pragma unroll
                    for (int q = 0; q < 16; ++q) s[q] += r[q];
                }
                float brA = s_bih[jl0*3+0] + s_bhh[jl0*3+0];
                float bzA = s_bih[jl0*3+1] + s_bhh[jl0*3+1];
                float biA = s_bih[jl0*3+2], bhA = s_bhh[jl0*3+2];
                float brB = s_bih[jl1*3+0] + s_bhh[jl1*3+0];
                float bzB = s_bih[jl1*3+1] + s_bhh[jl1*3+1];
                float biB = s_bih[jl1*3+2], bhB = s_bhh[jl1*3+2];
                float hnA0 = gru_cell(s[0]+brA, s[2]+bzA, s[4]+biA, s[6]+bhA, hp0);
                float hnA1 = gru_cell(s[1]+brA, s[3]+bzA, s[5]+biA, s[7]+bhA, hp1);
                float hnB0 = gru_cell(s[8]+brB, s[10]+bzB, s[12]+biB, s[14]+bhB, hp2);
                float hnB1 = gru_cell(s[9]+brB, s[11]+bzB, s[13]+biB, s[15]+bhB, hp3);
                hp0 = hnA0; hp1 = hnA1; hp2 = hnB0; hp3 = hnB1;
                int jp = (j0g >> 1) + wj;
                float4 hv = make_float4(hnA0, hnB0, hnA1, hnB1);
                __stcg((float4*)g_h + jp * 32 + lane, hv);
                __stcg((float2*)(g_rssm + ((size_t)(2*lane) * T_ + t) * R_ + j0g + jl0),
                       make_float2(hnA0, hnB0));
                __stcg((float2*)(g_rssm + ((size_t)(2*lane+1) * T_ + t) * R_ + j0g + jl0),
                       make_float2(hnA1, hnB1));
            }
            rA0 = 0; rA1 = 0; zA0 = 0; zA1 = 0; nA0 = 0; nA1 = 0;
            rB0 = 0; rB1 = 0; zB0 = 0; zB1 = 0; nB0 = 0; nB1 = 0;
        }

        grid_sync(2 * t + 1);
        cpa_team(tb0, hsrc, ttid); CP_COMMIT();

        ull P0 = 0, P1 = 0;
        for (int c = 0; c < 8; ++c) {
            CP_WAIT0(); teambar(team);
            if (c < 7) {
                cpa_team((c & 1) ? tb0 : tb1, hsrc + (c + 1) * 2048, ttid);
                CP_COMMIT();
            }
            const float* buf = (c & 1) ? sb1 : sb0;
            int off = c * 128 + team * 32;
            gchunk2<true>(buf, hhAr + off, hhAz + off, hhAn + off,
                          hhBr + off, hhBz + off, hhBn + off, wpR + off,
                          rA0, rA1, zA0, zA1, nA0, nA1,
                          rB0, rB1, zB0, zB1, nB0, nB1, P0, P1);
        }
        {
            __syncthreads();
            ull* red2 = (ull*)s_stg;
            *(ulonglong2*)(red2 + (size_t)(team * 4 + wj) * 64 + 2 * lane) =
                make_ulonglong2(P0, P1);
            __syncthreads();
            if (tid < 128) {
                int sl = tid >> 6, b = tid & 63;
                float m = px.x, v = px.y;
#pragma unroll
                for (int tm = 0; tm < 4; ++tm) {
                    m += sum2(red2[(size_t)(tm * 4 + 2 * sl) * 64 + b]);
                    v += sum2(red2[(size_t)(tm * 4 + 2 * sl + 1) * 64 + b]);
                }
                float zv = nz * __expf(0.5f * v) + m;
                int sg = s0g + sl;
                __stcg(&g_z[(size_t)(sg >> 1) * 128 + b * 2 + (sg & 1)], zv);
                g_rssm[((size_t)b * T_ + t) * R_ + D_ + sg] = zv;
            }
        }
        grid_sync(2 * t + 2);
        cpa_team(tb0, zsrc, ttid); CP_COMMIT();
    }
}

// ---------------------------------------------------------------------------
// Broadcast-layout f32x2 GEMM: tile 128x128x32, 256 thr, 1 blk/SM, 8x8 packed.
// smem rows: [row][16 k2-pairs + 2 pad] ull (144B rows, cp.async 16B-aligned).
// C = act(A[M,K] @ W[N,K]^T + bias)
// ---------------------------------------------------------------------------
#define GROW 18                       // ull per smem row (16 + 2 pad)
#define GBUF (128 * GROW)             // ull per buffer
#define G2_SMEM_BYTES (4 * GBUF * 8)  // A0,A1,W0,W1 = 73,728 B

__global__ void __launch_bounds__(256, 1) gemm_b_kernel(
    const float* __restrict__ A, const float* __restrict__ W,
    const float* __restrict__ bias, float* __restrict__ C,
    int M, int N, int K, int act)
{
    extern __shared__ ull sg2[];
    ull* sA[2] = { sg2, sg2 + GBUF };
    ull* sW[2] = { sg2 + 2 * GBUF, sg2 + 3 * GBUF };
    const unsigned su = smem_u32h(sg2);

    const int tid = threadIdx.x;
    const int bm = blockIdx.y * 128;
    const int bn = blockIdx.x * 128;
    const int tx = tid & 15, ty = tid >> 4;
    const int m0 = ty * 8, n0 = tx * 8;

    const int r = tid >> 1;                  // staging row 0..127
    const int sg0 = (tid & 1) * 4;           // first of 4 segs (16B each)
    const float* gA = A + (size_t)(bm + r) * K + sg0 * 4;
    const float* gW = W + (size_t)(bn + r) * K + sg0 * 4;
    const unsigned dA0 = su + (unsigned)(r * GROW * 8 + sg0 * 16);
    const unsigned dW0 = dA0 + (unsigned)(2 * GBUF * 8);

#define G2_STAGE(bi, kb) do { \
    unsigned _o = (unsigned)(bi) * (GBUF * 8); \
    const float* _a = gA + (size_t)(kb) * 32; \
    const float* _w = gW + (size_t)(kb) * 32; \
    cpa16(dA0 + _o,      _a);      cpa16(dA0 + _o + 16, _a + 4); \
    cpa16(dA0 + _o + 32, _a + 8);  cpa16(dA0 + _o + 48, _a + 12); \
    cpa16(dW0 + _o,      _w);      cpa16(dW0 + _o + 16, _w + 4); \
    cpa16(dW0 + _o + 32, _w + 8);  cpa16(dW0 + _o + 48, _w + 12); \
    CP_COMMIT(); \
} while (0)

    ull acc[8][8];
#pragma unroll
    for (int i = 0; i < 8; ++i)
#pragma unroll
        for (int j = 0; j < 8; ++j) acc[i][j] = 0ULL;

    const int niter = K / 32;
    G2_STAGE(0, 0);
    if (niter > 1) G2_STAGE(1, 1);

    for (int kb = 0; kb < niter; ++kb) {
        if (kb + 1 < niter) CP_WAIT1(); else CP_WAIT0();
        __syncthreads();
        const ull* bA = sA[kb & 1];
        const ull* bW = sW[kb & 1];
#pragma unroll
        for (int d = 0; d < 8; ++d) {        // double-k2: k2 = 2d, 2d+1
            ulonglong2 ra[8], rw[8];
#pragma unroll
            for (int i = 0; i < 8; ++i)
                ra[i] = *(const ulonglong2*)(bA + (m0 + i) * GROW + 2 * d);
#pragma unroll
            for (int j = 0; j < 8; ++j)
                rw[j] = *(const ulonglong2*)(bW + (n0 + j) * GROW + 2 * d);
#pragma unroll
            for (int i = 0; i < 8; ++i)
#pragma unroll
                for (int j = 0; j < 8; ++j) {
                    ffma2(acc[i][j], ra[i].x, rw[j].x);
                    ffma2(acc[i][j], ra[i].y, rw[j].y);
                }
        }
        __syncthreads();
        if (kb + 2 < niter) G2_STAGE(kb & 1, kb + 2);
    }

    float bb[8];
#pragma unroll
    for (int j = 0; j < 8; ++j) bb[j] = bias[bn + n0 + j];
#pragma unroll
    for (int i = 0; i < 8; ++i) {
        float rr[8];
#pragma unroll
        for (int j = 0; j < 8; ++j) {
            float v = sum2(acc[i][j]) + bb[j];
            rr[j] = act ? (v > 0.f ? v : expm1f(v)) : v;
        }
        float4* dst = (float4*)(C + (size_t)(bm + m0 + i) * N + bn + n0);
        dst[0] = make_float4(rr[0], rr[1], rr[2], rr[3]);
        dst[1] = make_float4(rr[4], rr[5], rr[6], rr[7]);
    }
}

__global__ void epilogue_kernel(const float* __restrict__ x, float* __restrict__ out) {
    size_t idx = (size_t)blockIdx.x * blockDim.x + threadIdx.x;
    const size_t total = (size_t)B_ * T_ * I_;
    if (idx >= total) return;
    int i = (int)(idx & (I_ - 1));
    size_t bt = idx >> 9;
    int t = (int)(bt & (T_ - 1));
    int b = (int)(bt >> 8);
    float xh;
    if (t == 0) xh = x[idx];
    else        xh = x[idx - I_] + g_dist[idx - I_];
    out[(size_t)B_ * (T_ - 1) * I_ + idx] = xh;
    if (t < T_ - 1)
        out[((size_t)b * (T_ - 1) + t) * I_ + i] = g_dist[idx];
}

extern "C" void kernel_launch(void* const* d_in, const int* in_sizes, int n_in,
                              void* d_out, int out_size) {
    const float* x     = (const float*)d_in[0];
    const float* noise = (const float*)d_in[1];
    const float* W_ih  = (const float*)d_in[2];
    const float* W_hh  = (const float*)d_in[3];
    const float* b_ih  = (const float*)d_in[4];
    const float* b_hh  = (const float*)d_in[5];
    const float* Wm    = (const float*)d_in[6];
    const float* bm    = (const float*)d_in[7];
    const float* Wv    = (const float*)d_in[8];
    const float* bv    = (const float*)d_in[9];
    const float* dW0   = (const float*)d_in[10];
    const float* db0   = (const float*)d_in[11];
    const float* dW1   = (const float*)d_in[12];
    const float* db1   = (const float*)d_in[13];
    const float* dW2   = (const float*)d_in[14];
    const float* db2   = (const float*)d_in[15];
    const float* dW3   = (const float*)d_in[16];
    const float* db3   = (const float*)d_in[17];
    float* out = (float*)d_out;

    cudaFuncSetAttribute(scan_kernel, cudaFuncAttributeMaxDynamicSharedMemorySize,
                         SCAN_SMEM_BYTES);
    cudaFuncSetAttribute(gemm_b_kernel, cudaFuncAttributeMaxDynamicSharedMemorySize,
                         G2_SMEM_BYTES);

    void *p_rssm, *p_a0, *p_a1, *p_dist, *p_wx, *p_bx, *p_postx;
    cudaGetSymbolAddress(&p_rssm, g_rssm);
    cudaGetSymbolAddress(&p_a0, g_a0);
    cudaGetSymbolAddress(&p_a1, g_a1);
    cudaGetSymbolAddress(&p_dist, g_dist);
    cudaGetSymbolAddress(&p_wx, g_wx);
    cudaGetSymbolAddress(&p_bx, g_bx);
    cudaGetSymbolAddress(&p_postx, g_postx);

    const int M = B_ * T_;  // 16384

    init_state_kernel<<<64, 256>>>();
    build_wx_kernel<<<2 * S_, 256>>>(Wm, Wv, bm, bv);

    gemm_b_kernel<<<dim3((2 * S_) / 128, M / 128), 256, G2_SMEM_BYTES>>>(
        x, (const float*)p_wx, (const float*)p_bx, (float*)p_postx,
        M, 2 * S_, I_, 0);

    scan_kernel<<<GBLK, TPB, SCAN_SMEM_BYTES>>>(W_ih, W_hh, b_ih, b_hh,
                                                Wm, Wv, noise);

    gemm_b_kernel<<<dim3(H_ / 128, M / 128), 256, G2_SMEM_BYTES>>>(
        (const float*)p_rssm, dW0, db0, (float*)p_a0, M, H_, R_, 1);
    gemm_b_kernel<<<dim3(H_ / 128, M / 128), 256, G2_SMEM_BYTES>>>(
        (const float*)p_a0, dW1, db1, (float*)p_a1, M, H_, H_, 1);
    gemm_b_kernel<<<dim3(H_ / 128, M / 128), 256, G2_SMEM_BYTES>>>(
        (const float*)p_a1, dW2, db2, (float*)p_a0, M, H_, H_, 1);
    gemm_b_kernel<<<dim3(I_ / 128, M / 128), 256, G2_SMEM_BYTES>>>(
        (const float*)p_a0, dW3, db3, (float*)p_dist, M, I_, H_, 0);

    epilogue_kernel<<<(B_ * T_ * I_ + 255) / 256, 256>>>(x, out);
}